// round 14
// baseline (speedup 1.0000x reference)
#include <cuda_runtime.h>
#include <cstdint>

#define BB    2048
#define TSEQ  512
#define HH    51
#define TTOT  544      // TSEQ + 32 future
#define NCTA  152      // one CTA per SM on GB300
#define NBIG  72       // first 72 CTAs take 14 elements, remaining 80 take 13
#define EPCMX 14
#define NTHR  512      // 2 groups x 64 j x 2 gate-split x 2 k-split
#define MPT   7        // elements per thread
#define NROW  52       // 51 real j rows + row 51 = wlin output row (in W2h)
#define WROW  120      // floats per (j,ks) half-row: 112 used; 120/4=30=2*15 -> conflict-free
#define HROW  56       // floats per element row in h arrays (52 used + 4 zero pad)

#define W_SZ   (2 * NROW * WROW)  // 12480 floats per weight matrix (104 half-rows)
#define XS_SZ  (EPCMX * TSEQ)     // 7168
#define HD_SZ  (EPCMX * HROW)     // 784
#define SM_FLOATS (3*W_SZ + XS_SZ + 2*HD_SZ + 256 + 256 + 256 + 16)
#define SM_BYTES  (SM_FLOATS * 4)

// ---------------- packed f32x2 helpers ----------------
__device__ __forceinline__ unsigned long long ffma2(unsigned long long a,
                                                    unsigned long long b,
                                                    unsigned long long c) {
    unsigned long long d;
    asm("fma.rn.f32x2 %0, %1, %2, %3;" : "=l"(d) : "l"(a), "l"(b), "l"(c));
    return d;
}
__device__ __forceinline__ float2 unpack2(unsigned long long v) {
    float2 r;
    asm("mov.b64 {%0, %1}, %2;" : "=f"(r.x), "=f"(r.y) : "l"(v));
    return r;
}
// ---------------- HW tanh activations (MUFU.TANH) ----------------
__device__ __forceinline__ float tanh_ap(float x) {
    float y;
    asm("tanh.approx.f32 %0, %1;" : "=f"(y) : "f"(x));
    return y;
}
__device__ __forceinline__ float sig_ap(float x) {
    return fmaf(0.5f, tanh_ap(0.5f * x), 0.5f);
}

// half-k matvec: acc{A,B}[m] += W[row(j,ks), gates(gs,gs+2), khalf] . h[e0+m, khalf]
__device__ __forceinline__ void matvec_acc(const float* __restrict__ Wthr,
                                           const float* __restrict__ hthr,
                                           unsigned long long aA[MPT],
                                           unsigned long long aB[MPT]) {
#pragma unroll
    for (int q = 0; q < 7; q++) {
        ulonglong2 wa = *(const ulonglong2*)(Wthr + q * 16);      // kpair (4q,4q+1)
        ulonglong2 wb = *(const ulonglong2*)(Wthr + q * 16 + 8);  // kpair (4q+2,4q+3)
#pragma unroll
        for (int m = 0; m < MPT; m++) {
            ulonglong2 hp = *(const ulonglong2*)(hthr + m * HROW + q * 4);
            aA[m] = ffma2(wa.x, hp.x, aA[m]);
            aB[m] = ffma2(wa.y, hp.x, aB[m]);
            aA[m] = ffma2(wb.x, hp.y, aA[m]);
            aB[m] = ffma2(wb.y, hp.y, aB[m]);
        }
    }
}

// shared-operand dual matvec: TWO weight matrices against the SAME h half-vector.
__device__ __forceinline__ void matvec_dual_sh(const float* __restrict__ Wr1,
                                               const float* __restrict__ Wr2,
                                               const float* __restrict__ h,
                                               unsigned long long aA[MPT],
                                               unsigned long long aB[MPT],
                                               unsigned long long aC[MPT],
                                               unsigned long long aD[MPT]) {
#pragma unroll
    for (int q = 0; q < 7; q++) {
        ulonglong2 wa1 = *(const ulonglong2*)(Wr1 + q * 16);
        ulonglong2 wb1 = *(const ulonglong2*)(Wr1 + q * 16 + 8);
        ulonglong2 wa2 = *(const ulonglong2*)(Wr2 + q * 16);
        ulonglong2 wb2 = *(const ulonglong2*)(Wr2 + q * 16 + 8);
#pragma unroll
        for (int m = 0; m < MPT; m++) {
            ulonglong2 hp = *(const ulonglong2*)(h + m * HROW + q * 4);
            aA[m] = ffma2(wa1.x, hp.x, aA[m]);
            aB[m] = ffma2(wa1.y, hp.x, aB[m]);
            aC[m] = ffma2(wa2.x, hp.x, aC[m]);
            aD[m] = ffma2(wa2.y, hp.x, aD[m]);
            aA[m] = ffma2(wb1.x, hp.y, aA[m]);
            aB[m] = ffma2(wb1.y, hp.y, aB[m]);
            aC[m] = ffma2(wb2.x, hp.y, aC[m]);
            aD[m] = ffma2(wb2.y, hp.y, aD[m]);
        }
    }
}

__global__ void __launch_bounds__(NTHR, 1)
lstm_seq_kernel(const float* __restrict__ input,
                const float* __restrict__ Wih1, const float* __restrict__ Whh1,
                const float* __restrict__ bih1, const float* __restrict__ bhh1,
                const float* __restrict__ Wih2, const float* __restrict__ Whh2,
                const float* __restrict__ bih2, const float* __restrict__ bhh2,
                const float* __restrict__ Wlin, const float* __restrict__ blin,
                float* __restrict__ out) {
    extern __shared__ float sm[];
    float* W1    = sm;                 // half-rows (2j+ks)*WROW; chunks [kbl][gs pair]
    float* W2i   = W1  + W_SZ;
    float* W2h   = W2i + W_SZ;         // row 51 gate-slot0 = wlin (output row)
    float* xs    = W2h + W_SZ;         // [14][512]
    float* hd1   = xs  + XS_SZ;        // [14][56]
    float* hd2   = hd1 + HD_SZ;        // [14][56]
    float* wih1q = hd2 + HD_SZ;        // [64][4] gate order i,f,g,o
    float* b1q   = wih1q + 256;
    float* b2q   = b1q   + 256;
    float* ovF   = b2q   + 256;        // [16] feedback distribution buffer

    const int tid = threadIdx.x;
    const int g   = tid >> 8;           // group 0..1
    const int r   = tid & 255;
    const int gs  = r & 1;              // lane bit0: gs0 -> gates (i,g); gs1 -> (f,o)
    const int ks  = (r >> 1) & 1;       // lane bit1: k-half
    const int j   = r >> 2;             // 0..63
    const int jj  = (j < NROW) ? j : (NROW - 1);
    const int cta = blockIdx.x;
    const int big = (cta < NBIG);
    const int epc = big ? 14 : 13;
    const int b0  = big ? cta * 14 : NBIG * 14 + (cta - NBIG) * 13;
    const int e0  = g * MPT;

    // a2 = cA * tanh(cM * z) + cB : gs0 -> tanh (gate g), gs1 -> sigmoid (gate o)
    const float cM = gs ? 0.5f : 1.0f;
    const float cA = gs ? 0.5f : 1.0f;
    const float cB = gs ? 0.5f : 0.0f;

    // ---------- one-time init ----------
    for (int idx = tid; idx < 3 * W_SZ; idx += NTHR) W1[idx] = 0.f;
    __syncthreads();
    // fill: (jr, kss, kbl) -> 8 floats (4 gates x 2 s)
    for (int idx = tid; idx < NROW * 28; idx += NTHR) {
        int jr  = idx / 28;
        int rem = idx - jr * 28;
        int kss = rem / 14;
        int kbl = rem - kss * 14;
        int base = (2 * jr + kss) * WROW + kbl * 8;
#pragma unroll
        for (int gg = 0; gg < 4; gg++) {
#pragma unroll
            for (int s = 0; s < 2; s++) {
                int k = kss * 28 + 2 * kbl + s;
                int o = base + (gg & 1) * 4 + (gg >> 1) * 2 + s;
                float v1 = 0.f, v2 = 0.f, v3 = 0.f;
                if (jr < HH && k < HH) {
                    int rr = gg * HH + jr;
                    v1 = Whh1[rr * HH + k];
                    v2 = Wih2[rr * HH + k];
                    v3 = Whh2[rr * HH + k];
                } else if (jr == HH && gg == 0 && k < HH) {
                    v3 = Wlin[k];                       // output row in W2h
                }
                W1 [o] = v1;
                W2i[o] = v2;
                W2h[o] = v3;
            }
        }
    }
    if (tid < 64) {
#pragma unroll
        for (int gg = 0; gg < 4; gg++) {
            bool ok = tid < HH;
            wih1q[tid * 4 + gg] = ok ? Wih1[gg * HH + tid] : 0.f;
            b1q  [tid * 4 + gg] = ok ? (bih1[gg * HH + tid] + bhh1[gg * HH + tid]) : 0.f;
            b2q  [tid * 4 + gg] = ok ? (bih2[gg * HH + tid] + bhh2[gg * HH + tid]) : 0.f;
        }
    }
    for (int idx = tid; idx < XS_SZ; idx += NTHR) {
        int e = idx >> 9, tc = idx & 511;
        xs[idx] = (e < epc) ? input[(size_t)(b0 + e) * TSEQ + tc] : 0.f;
    }
    for (int idx = tid; idx < 2 * HD_SZ; idx += NTHR) hd1[idx] = 0.f;
    if (tid < 16) ovF[tid] = 0.f;
    const float blin_r = blin[0];
    __syncthreads();

    float c1[MPT], c2[MPT], z2A[MPT], z2B[MPT];
#pragma unroll
    for (int m = 0; m < MPT; m++) { c1[m] = 0.f; c2[m] = 0.f; z2A[m] = 0.f; z2B[m] = 0.f; }

    const int rowI = 2 * jj + ks;
    const float*  W1r  = W1  + rowI * WROW + gs * 4;
    const float*  W2ir = W2i + rowI * WROW + gs * 4;
    const float*  W2hr = W2h + rowI * WROW + gs * 4;
    // my 2 gates: (gs, gs+2) in i,f,g,o order
    const float2  wxp  = make_float2(wih1q[jj * 4 + gs], wih1q[jj * 4 + 2 + gs]);
    const float2  bp1  = make_float2(b1q  [jj * 4 + gs], b1q  [jj * 4 + 2 + gs]);
    const float2  bp2  = make_float2(b2q  [jj * 4 + gs], b2q  [jj * 4 + 2 + gs]);
    const bool    outown = (r == 4 * HH);   // j==51, gs==0, ks==0
    const bool    hwr    = ((r & 3) == 1) && (j < HH);   // gs1,ks0 writer lane
    const float*  hd1g = hd1 + e0 * HROW + ks * 28;
    const float*  hd2g = hd2 + e0 * HROW + ks * 28;

    // ---------- prologue: h1(0) (h1(-1) = c1(-1) = 0; x-only, no k sum) ----------
#pragma unroll
    for (int m = 0; m < MPT; m++) {
        float x0 = xs[(e0 + m) * TSEQ];
        float zA = fmaf(wxp.x, x0, bp1.x);
        float zB = fmaf(wxp.y, x0, bp1.y);
        float a1 = sig_ap(zA);                          // i | f
        float a2 = fmaf(cA, tanh_ap(cM * zB), cB);      // g | o
        float ig  = a1 * a2;                            // valid gs0: i*g
        float igr = __shfl_xor_sync(0xffffffffu, ig, 1);
        c1[m] = igr;                                    // valid gs1: f*0 + i*g
        float h1n = a2 * tanh_ap(c1[m]);                // valid gs1
        if (hwr)
            hd1[(e0 + m) * HROW + j] = h1n;
    }
    __syncthreads();                                    // h1(0) visible

    // ---------- pipelined scan: iteration t emits h2(t), out(t), h1(t+1) ----------
    for (int t = 0; t < TTOT; t++) {
        // ---- phase A: dual over h1(t) half: mv2i(t) -> aA/aB, mv1(t+1) -> aC/aD ----
        unsigned long long aA[MPT], aB[MPT], aC[MPT], aD[MPT];
#pragma unroll
        for (int m = 0; m < MPT; m++) { aA[m] = 0; aB[m] = 0; aC[m] = 0; aD[m] = 0; }
        matvec_dual_sh(W2ir, W1r, hd1g, aA, aB, aC, aD);

        float z1A[MPT], z1B[MPT];                       // k-combined mv1(t+1) partials
#pragma unroll
        for (int m = 0; m < MPT; m++) {
            float2 vc = unpack2(aC[m]);
            float sC = vc.x + vc.y;
            z1A[m] = sC + __shfl_xor_sync(0xffffffffu, sC, 2);
            float2 vd = unpack2(aD[m]);
            float sD = vd.x + vd.y;
            z1B[m] = sD + __shfl_xor_sync(0xffffffffu, sD, 2);
        }

        // ---- combine2: h2(t)  (z2 = full mv2h(t) sums from phase B(t-1)) ----
#pragma unroll
        for (int m = 0; m < MPT; m++) {
            float2 va = unpack2(aA[m]);
            float sA = va.x + va.y;
            sA += __shfl_xor_sync(0xffffffffu, sA, 2);  // k-combine mv2i
            float2 vb = unpack2(aB[m]);
            float sB = vb.x + vb.y;
            sB += __shfl_xor_sync(0xffffffffu, sB, 2);
            float zA = sA + z2A[m] + bp2.x;
            float zB = sB + z2B[m] + bp2.y;
            float a1 = sig_ap(zA);                      // i | f
            float a2 = fmaf(cA, tanh_ap(cM * zB), cB);  // g | o
            float ig  = a1 * a2;
            float igr = __shfl_xor_sync(0xffffffffu, ig, 1);
            c2[m] = fmaf(a1, c2[m], igr);               // valid gs1
            float h2n = a2 * tanh_ap(c2[m]);            // valid gs1
            if (hwr)
                hd2[(e0 + m) * HROW + j] = h2n;
        }
        __syncthreads();                                // BAR-A: h2(t) visible

        // teacher-forced x(t+1)
        float xm[MPT];
        if (t + 1 < TSEQ) {
#pragma unroll
            for (int m = 0; m < MPT; m++) xm[m] = xs[(e0 + m) * TSEQ + (t + 1)];
        }

        // ---- phase B: mv2h(t+1) over h2(t) half; k-combine; row 51 -> out(t) ----
#pragma unroll
        for (int m = 0; m < MPT; m++) { aA[m] = 0; aB[m] = 0; }
        matvec_acc(W2hr, hd2g, aA, aB);
#pragma unroll
        for (int m = 0; m < MPT; m++) {
            float2 va = unpack2(aA[m]);
            float sA = va.x + va.y;
            z2A[m] = sA + __shfl_xor_sync(0xffffffffu, sA, 2);
            float2 vb = unpack2(aB[m]);
            float sB = vb.x + vb.y;
            z2B[m] = sB + __shfl_xor_sync(0xffffffffu, sB, 2);
        }

        // output-row owner emits out(t) directly from its full accumulator
        if (outown) {
#pragma unroll
            for (int m = 0; m < MPT; m++) {
                float o_t = z2A[m] + blin_r;
                if (e0 + m < epc)
                    out[(size_t)(b0 + e0 + m) * TTOT + t] = o_t;
                ovF[e0 + m] = o_t;                      // for feedback distribution
            }
        }
        if (t + 1 >= TSEQ) {                            // feedback steps: x(t+1) = out(t)
            __syncthreads();
#pragma unroll
            for (int m = 0; m < MPT; m++) xm[m] = ovF[e0 + m];
        }

        // ---- combine1: h1(t+1) from k-combined mv1 partials + x(t+1) ----
#pragma unroll
        for (int m = 0; m < MPT; m++) {
            float zA = z1A[m] + fmaf(wxp.x, xm[m], bp1.x);
            float zB = z1B[m] + fmaf(wxp.y, xm[m], bp1.y);
            float a1 = sig_ap(zA);
            float a2 = fmaf(cA, tanh_ap(cM * zB), cB);
            float ig  = a1 * a2;
            float igr = __shfl_xor_sync(0xffffffffu, ig, 1);
            c1[m] = fmaf(a1, c1[m], igr);
            float h1n = a2 * tanh_ap(c1[m]);
            if (hwr)
                hd1[(e0 + m) * HROW + j] = h1n;
        }
        __syncthreads();                                // BAR-B: h1(t+1) visible
    }
}

extern "C" void kernel_launch(void* const* d_in, const int* in_sizes, int n_in,
                              void* d_out, int out_size) {
    const float* input = (const float*)d_in[0];
    const float* Wih1  = (const float*)d_in[1];
    const float* Whh1  = (const float*)d_in[2];
    const float* bih1  = (const float*)d_in[3];
    const float* bhh1  = (const float*)d_in[4];
    const float* Wih2  = (const float*)d_in[5];
    const float* Whh2  = (const float*)d_in[6];
    const float* bih2  = (const float*)d_in[7];
    const float* bhh2  = (const float*)d_in[8];
    const float* Wlin  = (const float*)d_in[9];
    const float* blin  = (const float*)d_in[10];
    // d_in[11] = "future" (=32), baked in as a constant.

    cudaFuncSetAttribute(lstm_seq_kernel,
                         cudaFuncAttributeMaxDynamicSharedMemorySize, SM_BYTES);
    lstm_seq_kernel<<<NCTA, NTHR, SM_BYTES>>>(input, Wih1, Whh1, bih1, bhh1,
                                              Wih2, Whh2, bih2, bhh2,
                                              Wlin, blin, (float*)d_out);
}

// round 15
// speedup vs baseline: 1.2349x; 1.2349x over previous
#include <cuda_runtime.h>
#include <cstdint>

#define BB    2048
#define TSEQ  512
#define HH    51
#define TTOT  544      // TSEQ + 32 future
#define NCTA  128      // 128 CTAs x 16 elements = 2048 (no remainder guards)
#define EPC   16
#define NTHR  512      // 64 j x 2 gate-split x 4 m-split
#define M2    4        // elements per thread
#define NROW  52       // 51 real j rows + row 51 = wlin output row (in W2h)
#define WROW  232      // floats per j-row (conflict-free: warp weight set = 128B)
#define HROW  56       // floats per element row; +4 skew per 4-element block

#define W_SZ   (NROW * WROW)        // 12064 floats per weight matrix
#define XS_SZ  (EPC * 512 + 32)     // skewed x rows
#define HD_SZ  (EPC * HROW + 16)    // 912 floats per h array (with skew)
#define SM_FLOATS (3*W_SZ + XS_SZ + 2*HD_SZ + 256 + 256 + 256 + 16)
#define SM_BYTES  (SM_FLOATS * 4)

// skewed h index: hIdx(e) = e*56 + (e>>2)*4  (e = 4*ms + mi -> ms*228 + mi*56)
// skewed x index: xIdx(e) = e*512 + (e>>2)*8 (-> ms*2056 + mi*512)

// ---------------- packed f32x2 helpers ----------------
__device__ __forceinline__ unsigned long long ffma2(unsigned long long a,
                                                    unsigned long long b,
                                                    unsigned long long c) {
    unsigned long long d;
    asm("fma.rn.f32x2 %0, %1, %2, %3;" : "=l"(d) : "l"(a), "l"(b), "l"(c));
    return d;
}
__device__ __forceinline__ float2 unpack2(unsigned long long v) {
    float2 r;
    asm("mov.b64 {%0, %1}, %2;" : "=f"(r.x), "=f"(r.y) : "l"(v));
    return r;
}
// ---------------- HW tanh activations (MUFU.TANH) ----------------
__device__ __forceinline__ float tanh_ap(float x) {
    float y;
    asm("tanh.approx.f32 %0, %1;" : "=f"(y) : "f"(x));
    return y;
}
__device__ __forceinline__ float sig_ap(float x) {
    return fmaf(0.5f, tanh_ap(0.5f * x), 0.5f);
}

// single matvec over full k: acc{A,B}[mi] += W[j, gates(gs,gs+2), :] . h[e(mi), :]
__device__ __forceinline__ void matvec_acc(const float* __restrict__ Wrow,
                                           const float* __restrict__ hthr,
                                           unsigned long long aA[M2],
                                           unsigned long long aB[M2]) {
#pragma unroll
    for (int q = 0; q < 13; q++) {
        ulonglong2 wa = *(const ulonglong2*)(Wrow + q * 16);
        ulonglong2 wb = *(const ulonglong2*)(Wrow + q * 16 + 8);
#pragma unroll
        for (int mi = 0; mi < M2; mi++) {
            ulonglong2 hp = *(const ulonglong2*)(hthr + mi * HROW + q * 4);
            aA[mi] = ffma2(wa.x, hp.x, aA[mi]);
            aB[mi] = ffma2(wa.y, hp.x, aB[mi]);
            aA[mi] = ffma2(wb.x, hp.y, aA[mi]);
            aB[mi] = ffma2(wb.y, hp.y, aB[mi]);
        }
    }
}

// shared-operand dual matvec: TWO weight matrices against the SAME h vectors.
__device__ __forceinline__ void matvec_dual_sh(const float* __restrict__ Wr1,
                                               const float* __restrict__ Wr2,
                                               const float* __restrict__ hthr,
                                               unsigned long long aA[M2],
                                               unsigned long long aB[M2],
                                               unsigned long long aC[M2],
                                               unsigned long long aD[M2]) {
#pragma unroll
    for (int q = 0; q < 13; q++) {
        ulonglong2 wa1 = *(const ulonglong2*)(Wr1 + q * 16);
        ulonglong2 wb1 = *(const ulonglong2*)(Wr1 + q * 16 + 8);
        ulonglong2 wa2 = *(const ulonglong2*)(Wr2 + q * 16);
        ulonglong2 wb2 = *(const ulonglong2*)(Wr2 + q * 16 + 8);
#pragma unroll
        for (int mi = 0; mi < M2; mi++) {
            ulonglong2 hp = *(const ulonglong2*)(hthr + mi * HROW + q * 4);
            aA[mi] = ffma2(wa1.x, hp.x, aA[mi]);
            aB[mi] = ffma2(wa1.y, hp.x, aB[mi]);
            aC[mi] = ffma2(wa2.x, hp.x, aC[mi]);
            aD[mi] = ffma2(wa2.y, hp.x, aD[mi]);
            aA[mi] = ffma2(wb1.x, hp.y, aA[mi]);
            aB[mi] = ffma2(wb1.y, hp.y, aB[mi]);
            aC[mi] = ffma2(wb2.x, hp.y, aC[mi]);
            aD[mi] = ffma2(wb2.y, hp.y, aD[mi]);
        }
    }
}

__global__ void __launch_bounds__(NTHR, 1)
lstm_seq_kernel(const float* __restrict__ input,
                const float* __restrict__ Wih1, const float* __restrict__ Whh1,
                const float* __restrict__ bih1, const float* __restrict__ bhh1,
                const float* __restrict__ Wih2, const float* __restrict__ Whh2,
                const float* __restrict__ bih2, const float* __restrict__ bhh2,
                const float* __restrict__ Wlin, const float* __restrict__ blin,
                float* __restrict__ out) {
    extern __shared__ float sm[];
    float* W1    = sm;                 // gate slots per kb: [(i,g) pair][(f,o) pair]
    float* W2i   = W1  + W_SZ;
    float* W2h   = W2i + W_SZ;         // row 51 gate-slot0 = wlin (output row)
    float* xs    = W2h + W_SZ;         // skewed [16][512]
    float* hd1   = xs  + XS_SZ;        // skewed [16][56]
    float* hd2   = hd1 + HD_SZ;
    float* wih1q = hd2 + HD_SZ;        // [64][4] gate order i,f,g,o
    float* b1q   = wih1q + 256;
    float* b2q   = b1q   + 256;
    float* ovF   = b2q   + 256;        // [16] feedback distribution buffer

    const int tid = threadIdx.x;
    const int gs  = tid & 1;            // gs0 -> gates (i,g); gs1 -> gates (f,o)
    const int ms  = (tid >> 1) & 3;     // m-split: elements 4ms .. 4ms+3
    const int j   = tid >> 3;           // 0..63 (real < 51; 51 = output row)
    const int jj  = (j < NROW) ? j : (NROW - 1);
    const int b0  = blockIdx.x * EPC;

    // a2 = cA * tanh(cM * z) + cB : gs0 -> tanh (gate g), gs1 -> sigmoid (gate o)
    const float cM = gs ? 0.5f : 1.0f;
    const float cA = gs ? 0.5f : 1.0f;
    const float cB = gs ? 0.5f : 0.0f;

    // ---------- one-time init ----------
    // gate gg -> slot offset (gg&1)*4 + (gg>>1)*2 : pairs (i,g) at gs0, (f,o) at gs1
    for (int idx = tid; idx < NROW * 26; idx += NTHR) {
        int jr = idx / 26;
        int kb = idx - jr * 26;
#pragma unroll
        for (int gg = 0; gg < 4; gg++) {
#pragma unroll
            for (int s = 0; s < 2; s++) {
                int k = 2 * kb + s;
                bool ok = (k < HH);
                int o = jr * WROW + kb * 8 + (gg & 1) * 4 + (gg >> 1) * 2 + s;
                float v1 = 0.f, v2 = 0.f, v3 = 0.f;
                if (jr < HH && ok) {
                    int rr = gg * HH + jr;
                    v1 = Whh1[rr * HH + k];
                    v2 = Wih2[rr * HH + k];
                    v3 = Whh2[rr * HH + k];
                } else if (jr == HH && gg == 0 && ok) {
                    v3 = Wlin[k];                       // output row in W2h
                }
                W1 [o] = v1;
                W2i[o] = v2;
                W2h[o] = v3;
            }
        }
    }
    if (tid < 64) {
#pragma unroll
        for (int gg = 0; gg < 4; gg++) {
            bool ok = tid < HH;
            wih1q[tid * 4 + gg] = ok ? Wih1[gg * HH + tid] : 0.f;
            b1q  [tid * 4 + gg] = ok ? (bih1[gg * HH + tid] + bhh1[gg * HH + tid]) : 0.f;
            b2q  [tid * 4 + gg] = ok ? (bih2[gg * HH + tid] + bhh2[gg * HH + tid]) : 0.f;
        }
    }
    for (int idx = tid; idx < EPC * 512; idx += NTHR) {
        int e = idx >> 9, tc = idx & 511;
        xs[e * 512 + (e >> 2) * 8 + tc] = input[(size_t)(b0 + e) * TSEQ + tc];
    }
    for (int idx = tid; idx < 2 * HD_SZ; idx += NTHR) hd1[idx] = 0.f;
    if (tid < 16) ovF[tid] = 0.f;
    const float blin_r = blin[0];
    __syncthreads();

    float c1[M2], c2[M2], z2A[M2], z2B[M2];
#pragma unroll
    for (int mi = 0; mi < M2; mi++) { c1[mi] = 0.f; c2[mi] = 0.f; z2A[mi] = 0.f; z2B[mi] = 0.f; }

    const float*  W1r  = W1  + jj * WROW + gs * 4;
    const float*  W2ir = W2i + jj * WROW + gs * 4;
    const float*  W2hr = W2h + jj * WROW + gs * 4;
    const float2  wxp  = make_float2(wih1q[jj * 4 + gs], wih1q[jj * 4 + 2 + gs]);
    const float2  bp1  = make_float2(b1q  [jj * 4 + gs], b1q  [jj * 4 + 2 + gs]);
    const float2  bp2  = make_float2(b2q  [jj * 4 + gs], b2q  [jj * 4 + 2 + gs]);
    const bool    outown = (j == HH) && (gs == 0);      // output-row owner (4 ms lanes)
    const bool    hwr    = (gs == 1) && (j < HH);       // h writer lane
    const float*  hd1g = hd1 + ms * 228;                // skewed base (ms*228 floats)
    const float*  hd2g = hd2 + ms * 228;
    float*        h1wb = hd1 + ms * 228;
    float*        h2wb = hd2 + ms * 228;
    const float*  xsg  = xs + ms * 2056;                // ms*(4*512 + 8)

    // ---------- prologue: h1(0) (h1(-1) = c1(-1) = 0; x-only) ----------
#pragma unroll
    for (int mi = 0; mi < M2; mi++) {
        float x0 = xsg[mi * 512];
        float zA = fmaf(wxp.x, x0, bp1.x);
        float zB = fmaf(wxp.y, x0, bp1.y);
        float a1 = sig_ap(zA);                          // i | f
        float a2 = fmaf(cA, tanh_ap(cM * zB), cB);      // g | o
        float ig  = a1 * a2;                            // valid gs0: i*g
        float igr = __shfl_xor_sync(0xffffffffu, ig, 1);
        c1[mi] = igr;                                   // valid gs1: f*0 + i*g
        float h1n = a2 * tanh_ap(c1[mi]);               // valid gs1
        if (hwr)
            h1wb[mi * HROW + j] = h1n;
    }
    __syncthreads();                                    // h1(0) visible

    // ---------- pipelined scan: iteration t emits h2(t), out(t), h1(t+1) ----------
    for (int t = 0; t < TTOT; t++) {
        // ---- phase A: dual over h1(t): mv2i(t) -> aA/aB, mv1(t+1) -> aC/aD ----
        unsigned long long aA[M2], aB[M2], aC[M2], aD[M2];
#pragma unroll
        for (int mi = 0; mi < M2; mi++) { aA[mi] = 0; aB[mi] = 0; aC[mi] = 0; aD[mi] = 0; }
        matvec_dual_sh(W2ir, W1r, hd1g, aA, aB, aC, aD);

        float z1A[M2], z1B[M2];                         // compress mv1(t+1) partials
#pragma unroll
        for (int mi = 0; mi < M2; mi++) {
            float2 vc = unpack2(aC[mi]); z1A[mi] = vc.x + vc.y;
            float2 vd = unpack2(aD[mi]); z1B[mi] = vd.x + vd.y;
        }

        // ---- combine2: h2(t)  (z2 = mv2h(t) sums from phase B(t-1)) ----
#pragma unroll
        for (int mi = 0; mi < M2; mi++) {
            float2 va = unpack2(aA[mi]);
            float2 vb = unpack2(aB[mi]);
            float zA = va.x + va.y + z2A[mi] + bp2.x;
            float zB = vb.x + vb.y + z2B[mi] + bp2.y;
            float a1 = sig_ap(zA);                      // i | f
            float a2 = fmaf(cA, tanh_ap(cM * zB), cB);  // g | o
            float ig  = a1 * a2;
            float igr = __shfl_xor_sync(0xffffffffu, ig, 1);
            c2[mi] = fmaf(a1, c2[mi], igr);             // valid gs1
            float h2n = a2 * tanh_ap(c2[mi]);           // valid gs1
            if (hwr)
                h2wb[mi * HROW + j] = h2n;
        }
        __syncthreads();                                // BAR-A: h2(t) visible

        // teacher-forced x(t+1)
        float xm[M2];
        if (t + 1 < TSEQ) {
#pragma unroll
            for (int mi = 0; mi < M2; mi++) xm[mi] = xsg[mi * 512 + (t + 1)];
        }

        // ---- phase B: mv2h(t+1) over h2(t); row 51 slot0 = wlin -> out(t) ----
#pragma unroll
        for (int mi = 0; mi < M2; mi++) { aA[mi] = 0; aB[mi] = 0; }
        matvec_acc(W2hr, hd2g, aA, aB);
#pragma unroll
        for (int mi = 0; mi < M2; mi++) {
            float2 va = unpack2(aA[mi]); z2A[mi] = va.x + va.y;
            float2 vb = unpack2(aB[mi]); z2B[mi] = vb.x + vb.y;
        }

        // output-row owners emit out(t) directly from their accumulators
        if (outown) {
#pragma unroll
            for (int mi = 0; mi < M2; mi++) {
                float o_t = z2A[mi] + blin_r;
                out[(size_t)(b0 + 4 * ms + mi) * TTOT + t] = o_t;
                ovF[4 * ms + mi] = o_t;                 // for feedback distribution
            }
        }
        if (t + 1 >= TSEQ) {                            // feedback: x(t+1) = out(t)
            __syncthreads();
#pragma unroll
            for (int mi = 0; mi < M2; mi++) xm[mi] = ovF[4 * ms + mi];
        }

        // ---- combine1: h1(t+1) from mv1 partials + x(t+1) ----
#pragma unroll
        for (int mi = 0; mi < M2; mi++) {
            float zA = z1A[mi] + fmaf(wxp.x, xm[mi], bp1.x);
            float zB = z1B[mi] + fmaf(wxp.y, xm[mi], bp1.y);
            float a1 = sig_ap(zA);
            float a2 = fmaf(cA, tanh_ap(cM * zB), cB);
            float ig  = a1 * a2;
            float igr = __shfl_xor_sync(0xffffffffu, ig, 1);
            c1[mi] = fmaf(a1, c1[mi], igr);
            float h1n = a2 * tanh_ap(c1[mi]);
            if (hwr)
                h1wb[mi * HROW + j] = h1n;
        }
        __syncthreads();                                // BAR-B: h1(t+1) visible
    }
}

extern "C" void kernel_launch(void* const* d_in, const int* in_sizes, int n_in,
                              void* d_out, int out_size) {
    const float* input = (const float*)d_in[0];
    const float* Wih1  = (const float*)d_in[1];
    const float* Whh1  = (const float*)d_in[2];
    const float* bih1  = (const float*)d_in[3];
    const float* bhh1  = (const float*)d_in[4];
    const float* Wih2  = (const float*)d_in[5];
    const float* Whh2  = (const float*)d_in[6];
    const float* bih2  = (const float*)d_in[7];
    const float* bhh2  = (const float*)d_in[8];
    const float* Wlin  = (const float*)d_in[9];
    const float* blin  = (const float*)d_in[10];
    // d_in[11] = "future" (=32), baked in as a constant.

    cudaFuncSetAttribute(lstm_seq_kernel,
                         cudaFuncAttributeMaxDynamicSharedMemorySize, SM_BYTES);
    lstm_seq_kernel<<<NCTA, NTHR, SM_BYTES>>>(input, Wih1, Whh1, bih1, bhh1,
                                              Wih2, Whh2, bih2, bhh2,
                                              Wlin, blin, (float*)d_out);
}

// round 16
// speedup vs baseline: 1.2350x; 1.0001x over previous
#include <cuda_runtime.h>
#include <cstdint>

#define BB    2048
#define TSEQ  512
#define HH    51
#define TTOT  544      // TSEQ + 32 future
#define NCTA  128      // 128 CTAs x 16 elements = 2048 (no remainder guards)
#define EPC   16
#define NTHR  512      // 64 j x 2 gate-split x 4 m-split
#define M2    4        // elements per thread
#define NROW  52       // 51 real j rows + row 51 = wlin output row (in W2h)
#define WROW  232      // floats per j-row (conflict-free: warp weight set = 128B)
#define HROW  56       // floats per element row; +4 skew per 4-element block

#define W_SZ   (NROW * WROW)        // 12064 floats per weight matrix
#define XS_SZ  (EPC * 512 + 32)     // skewed x rows
#define HD_SZ  (EPC * HROW + 16)    // 912 floats per h array (with skew)
#define SM_FLOATS (3*W_SZ + XS_SZ + 2*HD_SZ + 256 + 256 + 256 + 16)
#define SM_BYTES  (SM_FLOATS * 4)

// skewed h index: hIdx(e) = e*56 + (e>>2)*4  (e = 4*ms + mi -> ms*228 + mi*56)
// skewed x index: xIdx(e) = e*512 + (e>>2)*8 (-> ms*2056 + mi*512)

// ---------------- packed f32x2 helpers ----------------
__device__ __forceinline__ unsigned long long ffma2(unsigned long long a,
                                                    unsigned long long b,
                                                    unsigned long long c) {
    unsigned long long d;
    asm("fma.rn.f32x2 %0, %1, %2, %3;" : "=l"(d) : "l"(a), "l"(b), "l"(c));
    return d;
}
__device__ __forceinline__ float2 unpack2(unsigned long long v) {
    float2 r;
    asm("mov.b64 {%0, %1}, %2;" : "=f"(r.x), "=f"(r.y) : "l"(v));
    return r;
}
// ---------------- HW tanh activations (MUFU.TANH) ----------------
__device__ __forceinline__ float tanh_ap(float x) {
    float y;
    asm("tanh.approx.f32 %0, %1;" : "=f"(y) : "f"(x));
    return y;
}
__device__ __forceinline__ float sig_ap(float x) {
    return fmaf(0.5f, tanh_ap(0.5f * x), 0.5f);
}

// single matvec over full k: acc{A,B}[mi] += W[j, gates(gs,gs+2), :] . h[e(mi), :]
__device__ __forceinline__ void matvec_acc(const float* __restrict__ Wrow,
                                           const float* __restrict__ hthr,
                                           unsigned long long aA[M2],
                                           unsigned long long aB[M2]) {
#pragma unroll
    for (int q = 0; q < 13; q++) {
        ulonglong2 wa = *(const ulonglong2*)(Wrow + q * 16);
        ulonglong2 wb = *(const ulonglong2*)(Wrow + q * 16 + 8);
#pragma unroll
        for (int mi = 0; mi < M2; mi++) {
            ulonglong2 hp = *(const ulonglong2*)(hthr + mi * HROW + q * 4);
            aA[mi] = ffma2(wa.x, hp.x, aA[mi]);
            aB[mi] = ffma2(wa.y, hp.x, aB[mi]);
            aA[mi] = ffma2(wb.x, hp.y, aA[mi]);
            aB[mi] = ffma2(wb.y, hp.y, aB[mi]);
        }
    }
}

// shared-operand dual matvec: TWO weight matrices against the SAME h vectors.
__device__ __forceinline__ void matvec_dual_sh(const float* __restrict__ Wr1,
                                               const float* __restrict__ Wr2,
                                               const float* __restrict__ hthr,
                                               unsigned long long aA[M2],
                                               unsigned long long aB[M2],
                                               unsigned long long aC[M2],
                                               unsigned long long aD[M2]) {
#pragma unroll
    for (int q = 0; q < 13; q++) {
        ulonglong2 wa1 = *(const ulonglong2*)(Wr1 + q * 16);
        ulonglong2 wb1 = *(const ulonglong2*)(Wr1 + q * 16 + 8);
        ulonglong2 wa2 = *(const ulonglong2*)(Wr2 + q * 16);
        ulonglong2 wb2 = *(const ulonglong2*)(Wr2 + q * 16 + 8);
#pragma unroll
        for (int mi = 0; mi < M2; mi++) {
            ulonglong2 hp = *(const ulonglong2*)(hthr + mi * HROW + q * 4);
            aA[mi] = ffma2(wa1.x, hp.x, aA[mi]);
            aB[mi] = ffma2(wa1.y, hp.x, aB[mi]);
            aC[mi] = ffma2(wa2.x, hp.x, aC[mi]);
            aD[mi] = ffma2(wa2.y, hp.x, aD[mi]);
            aA[mi] = ffma2(wb1.x, hp.y, aA[mi]);
            aB[mi] = ffma2(wb1.y, hp.y, aB[mi]);
            aC[mi] = ffma2(wb2.x, hp.y, aC[mi]);
            aD[mi] = ffma2(wb2.y, hp.y, aD[mi]);
        }
    }
}

__global__ void __launch_bounds__(NTHR, 1)
lstm_seq_kernel(const float* __restrict__ input,
                const float* __restrict__ Wih1, const float* __restrict__ Whh1,
                const float* __restrict__ bih1, const float* __restrict__ bhh1,
                const float* __restrict__ Wih2, const float* __restrict__ Whh2,
                const float* __restrict__ bih2, const float* __restrict__ bhh2,
                const float* __restrict__ Wlin, const float* __restrict__ blin,
                float* __restrict__ out) {
    extern __shared__ float sm[];
    float* W1    = sm;                 // gate slots per kb: [(i,g) pair][(f,o) pair]
    float* W2i   = W1  + W_SZ;
    float* W2h   = W2i + W_SZ;         // row 51 gate-slot0 = wlin (output row)
    float* xs    = W2h + W_SZ;         // skewed [16][512]
    float* hd1   = xs  + XS_SZ;        // skewed [16][56]
    float* hd2   = hd1 + HD_SZ;
    float* wih1q = hd2 + HD_SZ;        // [64][4] gate order i,f,g,o
    float* b1q   = wih1q + 256;
    float* b2q   = b1q   + 256;
    float* ovF   = b2q   + 256;        // [16] feedback distribution buffer

    const int tid = threadIdx.x;
    const int gs  = tid & 1;            // gs0 -> gates (i,g); gs1 -> gates (f,o)
    const int ms  = (tid >> 1) & 3;     // m-split: elements 4ms .. 4ms+3
    const int j   = tid >> 3;           // 0..63 (real < 51; 51 = output row)
    const int jj  = (j < NROW) ? j : (NROW - 1);
    const int b0  = blockIdx.x * EPC;

    // a2 = cA * tanh(cM * z) + cB : gs0 -> tanh (gate g), gs1 -> sigmoid (gate o)
    const float cM = gs ? 0.5f : 1.0f;
    const float cA = gs ? 0.5f : 1.0f;
    const float cB = gs ? 0.5f : 0.0f;

    // ---------- one-time init ----------
    // gate gg -> slot offset (gg&1)*4 + (gg>>1)*2 : pairs (i,g) at gs0, (f,o) at gs1
    for (int idx = tid; idx < NROW * 26; idx += NTHR) {
        int jr = idx / 26;
        int kb = idx - jr * 26;
#pragma unroll
        for (int gg = 0; gg < 4; gg++) {
#pragma unroll
            for (int s = 0; s < 2; s++) {
                int k = 2 * kb + s;
                bool ok = (k < HH);
                int o = jr * WROW + kb * 8 + (gg & 1) * 4 + (gg >> 1) * 2 + s;
                float v1 = 0.f, v2 = 0.f, v3 = 0.f;
                if (jr < HH && ok) {
                    int rr = gg * HH + jr;
                    v1 = Whh1[rr * HH + k];
                    v2 = Wih2[rr * HH + k];
                    v3 = Whh2[rr * HH + k];
                } else if (jr == HH && gg == 0 && ok) {
                    v3 = Wlin[k];                       // output row in W2h
                }
                W1 [o] = v1;
                W2i[o] = v2;
                W2h[o] = v3;
            }
        }
    }
    if (tid < 64) {
#pragma unroll
        for (int gg = 0; gg < 4; gg++) {
            bool ok = tid < HH;
            wih1q[tid * 4 + gg] = ok ? Wih1[gg * HH + tid] : 0.f;
            b1q  [tid * 4 + gg] = ok ? (bih1[gg * HH + tid] + bhh1[gg * HH + tid]) : 0.f;
            b2q  [tid * 4 + gg] = ok ? (bih2[gg * HH + tid] + bhh2[gg * HH + tid]) : 0.f;
        }
    }
    for (int idx = tid; idx < EPC * 512; idx += NTHR) {
        int e = idx >> 9, tc = idx & 511;
        xs[e * 512 + (e >> 2) * 8 + tc] = input[(size_t)(b0 + e) * TSEQ + tc];
    }
    for (int idx = tid; idx < 2 * HD_SZ; idx += NTHR) hd1[idx] = 0.f;
    if (tid < 16) ovF[tid] = 0.f;
    const float blin_r = blin[0];
    __syncthreads();

    float c1[M2], c2[M2], z2A[M2], z2B[M2];
#pragma unroll
    for (int mi = 0; mi < M2; mi++) { c1[mi] = 0.f; c2[mi] = 0.f; z2A[mi] = 0.f; z2B[mi] = 0.f; }

    const float*  W1r  = W1  + jj * WROW + gs * 4;
    const float*  W2ir = W2i + jj * WROW + gs * 4;
    const float*  W2hr = W2h + jj * WROW + gs * 4;
    const float2  wxp  = make_float2(wih1q[jj * 4 + gs], wih1q[jj * 4 + 2 + gs]);
    const float2  bp1  = make_float2(b1q  [jj * 4 + gs], b1q  [jj * 4 + 2 + gs]);
    const float2  bp2  = make_float2(b2q  [jj * 4 + gs], b2q  [jj * 4 + 2 + gs]);
    const bool    outown = (j == HH) && (gs == 0);      // output-row owner (4 ms lanes)
    const bool    hwr    = (gs == 1) && (j < HH);       // h writer lane
    const float*  hd1g = hd1 + ms * 228;                // skewed base (ms*228 floats)
    const float*  hd2g = hd2 + ms * 228;
    float*        h1wb = hd1 + ms * 228;
    float*        h2wb = hd2 + ms * 228;
    const float*  xsg  = xs + ms * 2056;                // ms*(4*512 + 8)

    // ---------- prologue: h1(0) (h1(-1) = c1(-1) = 0; x-only) ----------
#pragma unroll
    for (int mi = 0; mi < M2; mi++) {
        float x0 = xsg[mi * 512];
        float zA = fmaf(wxp.x, x0, bp1.x);
        float zB = fmaf(wxp.y, x0, bp1.y);
        float a1 = sig_ap(zA);                          // i | f
        float a2 = fmaf(cA, tanh_ap(cM * zB), cB);      // g | o
        float ig  = a1 * a2;                            // valid gs0: i*g
        float igr = __shfl_xor_sync(0xffffffffu, ig, 1);
        c1[mi] = igr;                                   // valid gs1: f*0 + i*g
        float h1n = a2 * tanh_ap(c1[mi]);               // valid gs1
        if (hwr)
            h1wb[mi * HROW + j] = h1n;
    }
    __syncthreads();                                    // h1(0) visible

    // ---------- pipelined scan: iteration t emits h2(t), out(t), h1(t+1) ----------
    for (int t = 0; t < TTOT; t++) {
        // ---- phase A: dual over h1(t): mv2i(t) -> aA/aB, mv1(t+1) -> aC/aD ----
        unsigned long long aA[M2], aB[M2], aC[M2], aD[M2];
#pragma unroll
        for (int mi = 0; mi < M2; mi++) { aA[mi] = 0; aB[mi] = 0; aC[mi] = 0; aD[mi] = 0; }
        matvec_dual_sh(W2ir, W1r, hd1g, aA, aB, aC, aD);

        float z1A[M2], z1B[M2];                         // compress mv1(t+1) partials
#pragma unroll
        for (int mi = 0; mi < M2; mi++) {
            float2 vc = unpack2(aC[mi]); z1A[mi] = vc.x + vc.y;
            float2 vd = unpack2(aD[mi]); z1B[mi] = vd.x + vd.y;
        }

        // ---- combine2: h2(t)  (z2 = mv2h(t) sums from phase B(t-1)) ----
#pragma unroll
        for (int mi = 0; mi < M2; mi++) {
            float2 va = unpack2(aA[mi]);
            float2 vb = unpack2(aB[mi]);
            float zA = va.x + va.y + z2A[mi] + bp2.x;
            float zB = vb.x + vb.y + z2B[mi] + bp2.y;
            float a1 = sig_ap(zA);                      // i | f
            float a2 = fmaf(cA, tanh_ap(cM * zB), cB);  // g | o
            float ig  = a1 * a2;
            float igr = __shfl_xor_sync(0xffffffffu, ig, 1);
            c2[mi] = fmaf(a1, c2[mi], igr);             // valid gs1
            float h2n = a2 * tanh_ap(c2[mi]);           // valid gs1
            if (hwr)
                h2wb[mi * HROW + j] = h2n;
        }
        __syncthreads();                                // BAR-A: h2(t) visible

        // teacher-forced x(t+1)
        float xm[M2];
        if (t + 1 < TSEQ) {
#pragma unroll
            for (int mi = 0; mi < M2; mi++) xm[mi] = xsg[mi * 512 + (t + 1)];
        }

        // ---- phase B: mv2h(t+1) over h2(t); row 51 slot0 = wlin -> out(t) ----
#pragma unroll
        for (int mi = 0; mi < M2; mi++) { aA[mi] = 0; aB[mi] = 0; }
        matvec_acc(W2hr, hd2g, aA, aB);
#pragma unroll
        for (int mi = 0; mi < M2; mi++) {
            float2 va = unpack2(aA[mi]); z2A[mi] = va.x + va.y;
            float2 vb = unpack2(aB[mi]); z2B[mi] = vb.x + vb.y;
        }

        // output-row owners emit out(t) directly from their accumulators
        if (outown) {
#pragma unroll
            for (int mi = 0; mi < M2; mi++) {
                float o_t = z2A[mi] + blin_r;
                out[(size_t)(b0 + 4 * ms + mi) * TTOT + t] = o_t;
                ovF[4 * ms + mi] = o_t;                 // for feedback distribution
            }
        }
        if (t + 1 >= TSEQ) {                            // feedback: x(t+1) = out(t)
            __syncthreads();
#pragma unroll
            for (int mi = 0; mi < M2; mi++) xm[mi] = ovF[4 * ms + mi];
        }

        // ---- combine1: h1(t+1) from mv1 partials + x(t+1) ----
#pragma unroll
        for (int mi = 0; mi < M2; mi++) {
            float zA = z1A[mi] + fmaf(wxp.x, xm[mi], bp1.x);
            float zB = z1B[mi] + fmaf(wxp.y, xm[mi], bp1.y);
            float a1 = sig_ap(zA);
            float a2 = fmaf(cA, tanh_ap(cM * zB), cB);
            float ig  = a1 * a2;
            float igr = __shfl_xor_sync(0xffffffffu, ig, 1);
            c1[mi] = fmaf(a1, c1[mi], igr);
            float h1n = a2 * tanh_ap(c1[mi]);
            if (hwr)
                h1wb[mi * HROW + j] = h1n;
        }
        __syncthreads();                                // BAR-B: h1(t+1) visible
    }
}

extern "C" void kernel_launch(void* const* d_in, const int* in_sizes, int n_in,
                              void* d_out, int out_size) {
    const float* input = (const float*)d_in[0];
    const float* Wih1  = (const float*)d_in[1];
    const float* Whh1  = (const float*)d_in[2];
    const float* bih1  = (const float*)d_in[3];
    const float* bhh1  = (const float*)d_in[4];
    const float* Wih2  = (const float*)d_in[5];
    const float* Whh2  = (const float*)d_in[6];
    const float* bih2  = (const float*)d_in[7];
    const float* bhh2  = (const float*)d_in[8];
    const float* Wlin  = (const float*)d_in[9];
    const float* blin  = (const float*)d_in[10];
    // d_in[11] = "future" (=32), baked in as a constant.

    cudaFuncSetAttribute(lstm_seq_kernel,
                         cudaFuncAttributeMaxDynamicSharedMemorySize, SM_BYTES);
    lstm_seq_kernel<<<NCTA, NTHR, SM_BYTES>>>(input, Wih1, Whh1, bih1, bhh1,
                                              Wih2, Whh2, bih2, bhh2,
                                              Wlin, blin, (float*)d_out);
}

// round 17
// speedup vs baseline: 1.4047x; 1.1374x over previous
#include <cuda_runtime.h>
#include <cstdint>

#define BB    2048
#define TSEQ  512
#define HH    51
#define TTOT  544      // TSEQ + 32 future
#define NCTA  152      // one CTA per SM
#define NBIG  72       // 72 CTAs x 14 + 80 CTAs x 13 = 2048
#define EPCMX 14
#define NTHR  256      // 64 j x 2 m-split x 2 gate-split
#define M2    7        // elements per thread
#define NROW  52       // 51 real j rows + row 51 = wlin output row (in W2h)
#define WROW  228      // floats per j-row: 208 used; 228 % 32 == 4 -> 2-wf weight LDS
#define HROW  56       // floats per element row in h arrays
#define XROW  528      // skewed x row stride (16-float skew per element)

#define W_SZ   (NROW * WROW)      // 11856 floats per weight matrix
#define XS_SZ  (EPCMX * XROW)     // 7392
#define HD_SZ  (EPCMX * HROW)     // 784
#define SM_FLOATS (3*W_SZ + XS_SZ + 2*HD_SZ + 256 + 256 + 256 + 16)
#define SM_BYTES  (SM_FLOATS * 4)

// ---------------- packed f32x2 helpers ----------------
__device__ __forceinline__ unsigned long long ffma2(unsigned long long a,
                                                    unsigned long long b,
                                                    unsigned long long c) {
    unsigned long long d;
    asm("fma.rn.f32x2 %0, %1, %2, %3;" : "=l"(d) : "l"(a), "l"(b), "l"(c));
    return d;
}
__device__ __forceinline__ float2 unpack2(unsigned long long v) {
    float2 r;
    asm("mov.b64 {%0, %1}, %2;" : "=f"(r.x), "=f"(r.y) : "l"(v));
    return r;
}
// ---------------- HW tanh activations (MUFU.TANH) ----------------
__device__ __forceinline__ float tanh_ap(float x) {
    float y;
    asm("tanh.approx.f32 %0, %1;" : "=f"(y) : "f"(x));
    return y;
}
__device__ __forceinline__ float sig_ap(float x) {
    return fmaf(0.5f, tanh_ap(0.5f * x), 0.5f);
}

// single matvec over full k: acc{A,B}[mi] += W[j, gates(gs,gs+2), :] . h[e(mi), :]
__device__ __forceinline__ void matvec_acc(const float* __restrict__ Wrow,
                                           const float* __restrict__ hthr,
                                           unsigned long long aA[M2],
                                           unsigned long long aB[M2]) {
#pragma unroll
    for (int q = 0; q < 13; q++) {
        ulonglong2 wa = *(const ulonglong2*)(Wrow + q * 16);
        ulonglong2 wb = *(const ulonglong2*)(Wrow + q * 16 + 8);
#pragma unroll
        for (int mi = 0; mi < M2; mi++) {
            ulonglong2 hp = *(const ulonglong2*)(hthr + mi * HROW + q * 4);
            aA[mi] = ffma2(wa.x, hp.x, aA[mi]);
            aB[mi] = ffma2(wa.y, hp.x, aB[mi]);
            aA[mi] = ffma2(wb.x, hp.y, aA[mi]);
            aB[mi] = ffma2(wb.y, hp.y, aB[mi]);
        }
    }
}

// shared-operand dual matvec: TWO weight matrices against the SAME h vectors.
__device__ __forceinline__ void matvec_dual_sh(const float* __restrict__ Wr1,
                                               const float* __restrict__ Wr2,
                                               const float* __restrict__ hthr,
                                               unsigned long long aA[M2],
                                               unsigned long long aB[M2],
                                               unsigned long long aC[M2],
                                               unsigned long long aD[M2]) {
#pragma unroll
    for (int q = 0; q < 13; q++) {
        ulonglong2 wa1 = *(const ulonglong2*)(Wr1 + q * 16);
        ulonglong2 wb1 = *(const ulonglong2*)(Wr1 + q * 16 + 8);
        ulonglong2 wa2 = *(const ulonglong2*)(Wr2 + q * 16);
        ulonglong2 wb2 = *(const ulonglong2*)(Wr2 + q * 16 + 8);
#pragma unroll
        for (int mi = 0; mi < M2; mi++) {
            ulonglong2 hp = *(const ulonglong2*)(hthr + mi * HROW + q * 4);
            aA[mi] = ffma2(wa1.x, hp.x, aA[mi]);
            aB[mi] = ffma2(wa1.y, hp.x, aB[mi]);
            aC[mi] = ffma2(wa2.x, hp.x, aC[mi]);
            aD[mi] = ffma2(wa2.y, hp.x, aD[mi]);
            aA[mi] = ffma2(wb1.x, hp.y, aA[mi]);
            aB[mi] = ffma2(wb1.y, hp.y, aB[mi]);
            aC[mi] = ffma2(wb2.x, hp.y, aC[mi]);
            aD[mi] = ffma2(wb2.y, hp.y, aD[mi]);
        }
    }
}

__global__ void __launch_bounds__(NTHR, 1)
lstm_seq_kernel(const float* __restrict__ input,
                const float* __restrict__ Wih1, const float* __restrict__ Whh1,
                const float* __restrict__ bih1, const float* __restrict__ bhh1,
                const float* __restrict__ Wih2, const float* __restrict__ Whh2,
                const float* __restrict__ bih2, const float* __restrict__ bhh2,
                const float* __restrict__ Wlin, const float* __restrict__ blin,
                float* __restrict__ out) {
    extern __shared__ float sm[];
    float* W1    = sm;                 // gate slots per kb: [(i,g) pair][(f,o) pair]
    float* W2i   = W1  + W_SZ;
    float* W2h   = W2i + W_SZ;         // row 51 gate-slot0 = wlin (output row)
    float* xs    = W2h + W_SZ;         // skewed [14][528]
    float* hd1   = xs  + XS_SZ;        // [14][56]
    float* hd2   = hd1 + HD_SZ;
    float* wih1q = hd2 + HD_SZ;        // [64][4] gate order i,f,g,o
    float* b1q   = wih1q + 256;
    float* b2q   = b1q   + 256;
    float* ovF   = b2q   + 256;        // [16] feedback distribution buffer

    const int tid = threadIdx.x;
    const int gs  = tid & 1;            // gs0 -> gates (i,g); gs1 -> gates (f,o)
    const int ms  = (tid >> 1) & 1;     // m-split: elements 7ms .. 7ms+6
    const int j   = tid >> 2;           // 0..63 (real < 51; 51 = output row)
    const int jj  = (j < NROW) ? j : (NROW - 1);
    const int cta = blockIdx.x;
    const int big = (cta < NBIG);
    const int epc = big ? 14 : 13;
    const int b0  = big ? cta * 14 : NBIG * 14 + (cta - NBIG) * 13;
    const int e0  = ms * M2;

    // a2 = cA * tanh(cM * z) + cB : gs0 -> tanh (gate g), gs1 -> sigmoid (gate o)
    const float cM = gs ? 0.5f : 1.0f;
    const float cA = gs ? 0.5f : 1.0f;
    const float cB = gs ? 0.5f : 0.0f;

    // ---------- one-time init ----------
    // gate gg -> slot offset (gg&1)*4 + (gg>>1)*2 : pairs (i,g) at gs0, (f,o) at gs1
    for (int idx = tid; idx < NROW * 26; idx += NTHR) {
        int jr = idx / 26;
        int kb = idx - jr * 26;
#pragma unroll
        for (int gg = 0; gg < 4; gg++) {
#pragma unroll
            for (int s = 0; s < 2; s++) {
                int k = 2 * kb + s;
                bool ok = (k < HH);
                int o = jr * WROW + kb * 8 + (gg & 1) * 4 + (gg >> 1) * 2 + s;
                float v1 = 0.f, v2 = 0.f, v3 = 0.f;
                if (jr < HH && ok) {
                    int rr = gg * HH + jr;
                    v1 = Whh1[rr * HH + k];
                    v2 = Wih2[rr * HH + k];
                    v3 = Whh2[rr * HH + k];
                } else if (jr == HH && gg == 0 && ok) {
                    v3 = Wlin[k];                       // output row in W2h
                }
                W1 [o] = v1;
                W2i[o] = v2;
                W2h[o] = v3;
            }
        }
    }
    if (tid < 64) {
#pragma unroll
        for (int gg = 0; gg < 4; gg++) {
            bool ok = tid < HH;
            wih1q[tid * 4 + gg] = ok ? Wih1[gg * HH + tid] : 0.f;
            b1q  [tid * 4 + gg] = ok ? (bih1[gg * HH + tid] + bhh1[gg * HH + tid]) : 0.f;
            b2q  [tid * 4 + gg] = ok ? (bih2[gg * HH + tid] + bhh2[gg * HH + tid]) : 0.f;
        }
    }
    for (int idx = tid; idx < EPCMX * 512; idx += NTHR) {
        int e = idx >> 9, tc = idx & 511;
        xs[e * XROW + tc] = (e < epc) ? input[(size_t)(b0 + e) * TSEQ + tc] : 0.f;
    }
    for (int idx = tid; idx < 2 * HD_SZ; idx += NTHR) hd1[idx] = 0.f;
    if (tid < 16) ovF[tid] = 0.f;
    const float blin_r = blin[0];
    __syncthreads();

    float c1[M2], c2[M2], z2A[M2], z2B[M2];
#pragma unroll
    for (int mi = 0; mi < M2; mi++) { c1[mi] = 0.f; c2[mi] = 0.f; z2A[mi] = 0.f; z2B[mi] = 0.f; }

    const float*  W1r  = W1  + jj * WROW + gs * 4;
    const float*  W2ir = W2i + jj * WROW + gs * 4;
    const float*  W2hr = W2h + jj * WROW + gs * 4;
    const float2  wxp  = make_float2(wih1q[jj * 4 + gs], wih1q[jj * 4 + 2 + gs]);
    const float2  bp1  = make_float2(b1q  [jj * 4 + gs], b1q  [jj * 4 + 2 + gs]);
    const float2  bp2  = make_float2(b2q  [jj * 4 + gs], b2q  [jj * 4 + 2 + gs]);
    const bool    outown = (j == HH) && (gs == 0);      // output-row owner (2 ms lanes)
    const bool    hwr    = (gs == 1) && (j < HH);       // h writer lane
    const float*  hd1g = hd1 + e0 * HROW;
    const float*  hd2g = hd2 + e0 * HROW;
    float*        h1wb = hd1 + e0 * HROW;
    float*        h2wb = hd2 + e0 * HROW;
    const float*  xsg  = xs + e0 * XROW;

    // ---------- prologue: h1(0) (h1(-1) = c1(-1) = 0; x-only) ----------
#pragma unroll
    for (int mi = 0; mi < M2; mi++) {
        float x0 = xsg[mi * XROW];
        float zA = fmaf(wxp.x, x0, bp1.x);
        float zB = fmaf(wxp.y, x0, bp1.y);
        float a1 = sig_ap(zA);                          // i | f
        float a2 = fmaf(cA, tanh_ap(cM * zB), cB);      // g | o
        float ig  = a1 * a2;                            // valid gs0: i*g
        float igr = __shfl_xor_sync(0xffffffffu, ig, 1);
        c1[mi] = igr;                                   // valid gs1: f*0 + i*g
        float h1n = a2 * tanh_ap(c1[mi]);               // valid gs1
        if (hwr)
            h1wb[mi * HROW + j] = h1n;
    }
    __syncthreads();                                    // h1(0) visible

    // ---------- pipelined scan: iteration t emits h2(t), out(t), h1(t+1) ----------
    for (int t = 0; t < TTOT; t++) {
        // ---- phase A: dual over h1(t): mv2i(t) -> aA/aB, mv1(t+1) -> aC/aD ----
        unsigned long long aA[M2], aB[M2], aC[M2], aD[M2];
#pragma unroll
        for (int mi = 0; mi < M2; mi++) { aA[mi] = 0; aB[mi] = 0; aC[mi] = 0; aD[mi] = 0; }
        matvec_dual_sh(W2ir, W1r, hd1g, aA, aB, aC, aD);

        float z1A[M2], z1B[M2];                         // compress mv1(t+1) partials
#pragma unroll
        for (int mi = 0; mi < M2; mi++) {
            float2 vc = unpack2(aC[mi]); z1A[mi] = vc.x + vc.y;
            float2 vd = unpack2(aD[mi]); z1B[mi] = vd.x + vd.y;
        }

        // ---- combine2: h2(t)  (z2 = mv2h(t) sums from phase B(t-1)) ----
#pragma unroll
        for (int mi = 0; mi < M2; mi++) {
            float2 va = unpack2(aA[mi]);
            float2 vb = unpack2(aB[mi]);
            float zA = va.x + va.y + z2A[mi] + bp2.x;
            float zB = vb.x + vb.y + z2B[mi] + bp2.y;
            float a1 = sig_ap(zA);                      // i | f
            float a2 = fmaf(cA, tanh_ap(cM * zB), cB);  // g | o
            float ig  = a1 * a2;
            float igr = __shfl_xor_sync(0xffffffffu, ig, 1);
            c2[mi] = fmaf(a1, c2[mi], igr);             // valid gs1
            float h2n = a2 * tanh_ap(c2[mi]);           // valid gs1
            if (hwr)
                h2wb[mi * HROW + j] = h2n;
        }
        __syncthreads();                                // BAR-A: h2(t) visible

        // teacher-forced x(t+1)
        float xm[M2];
        if (t + 1 < TSEQ) {
#pragma unroll
            for (int mi = 0; mi < M2; mi++) xm[mi] = xsg[mi * XROW + (t + 1)];
        }

        // ---- phase B: mv2h(t+1) over h2(t); row 51 slot0 = wlin -> out(t) ----
#pragma unroll
        for (int mi = 0; mi < M2; mi++) { aA[mi] = 0; aB[mi] = 0; }
        matvec_acc(W2hr, hd2g, aA, aB);
#pragma unroll
        for (int mi = 0; mi < M2; mi++) {
            float2 va = unpack2(aA[mi]); z2A[mi] = va.x + va.y;
            float2 vb = unpack2(aB[mi]); z2B[mi] = vb.x + vb.y;
        }

        // output-row owners emit out(t) directly from their accumulators
        if (outown) {
#pragma unroll
            for (int mi = 0; mi < M2; mi++) {
                float o_t = z2A[mi] + blin_r;
                if (e0 + mi < epc)
                    out[(size_t)(b0 + e0 + mi) * TTOT + t] = o_t;
                ovF[e0 + mi] = o_t;                     // for feedback distribution
            }
        }
        if (t + 1 >= TSEQ) {                            // feedback: x(t+1) = out(t)
            __syncthreads();
#pragma unroll
            for (int mi = 0; mi < M2; mi++) xm[mi] = ovF[e0 + mi];
        }

        // ---- combine1: h1(t+1) from mv1 partials + x(t+1) ----
#pragma unroll
        for (int mi = 0; mi < M2; mi++) {
            float zA = z1A[mi] + fmaf(wxp.x, xm[mi], bp1.x);
            float zB = z1B[mi] + fmaf(wxp.y, xm[mi], bp1.y);
            float a1 = sig_ap(zA);
            float a2 = fmaf(cA, tanh_ap(cM * zB), cB);
            float ig  = a1 * a2;
            float igr = __shfl_xor_sync(0xffffffffu, ig, 1);
            c1[mi] = fmaf(a1, c1[mi], igr);
            float h1n = a2 * tanh_ap(c1[mi]);
            if (hwr)
                h1wb[mi * HROW + j] = h1n;
        }
        __syncthreads();                                // BAR-B: h1(t+1) visible
    }
}

extern "C" void kernel_launch(void* const* d_in, const int* in_sizes, int n_in,
                              void* d_out, int out_size) {
    const float* input = (const float*)d_in[0];
    const float* Wih1  = (const float*)d_in[1];
    const float* Whh1  = (const float*)d_in[2];
    const float* bih1  = (const float*)d_in[3];
    const float* bhh1  = (const float*)d_in[4];
    const float* Wih2  = (const float*)d_in[5];
    const float* Whh2  = (const float*)d_in[6];
    const float* bih2  = (const float*)d_in[7];
    const float* bhh2  = (const float*)d_in[8];
    const float* Wlin  = (const float*)d_in[9];
    const float* blin  = (const float*)d_in[10];
    // d_in[11] = "future" (=32), baked in as a constant.

    cudaFuncSetAttribute(lstm_seq_kernel,
                         cudaFuncAttributeMaxDynamicSharedMemorySize, SM_BYTES);
    lstm_seq_kernel<<<NCTA, NTHR, SM_BYTES>>>(input, Wih1, Whh1, bih1, bhh1,
                                              Wih2, Whh2, bih2, bhh2,
                                              Wlin, blin, (float*)d_out);
}